// round 15
// baseline (speedup 1.0000x reference)
#include <cuda_runtime.h>
#include <cuda_bf16.h>
#include <cuda_fp16.h>
#include <cstdint>

#define BB 8
#define DD 128
#define LL 2048
#define HH 8
#define DHH 16
#define QSCALE 0.3606737602222409f  // DH^-0.5 * log2(e)

// Scratch
__device__ __align__(16) uint32_t g_Qhf[BB * HH * LL * 8];    // Q fp16 [bh][l][dh/2]
__device__ __align__(16) uint32_t g_Khf[BB * HH * LL * 8];    // K fp16 [bh][pos][dh/2]
__device__ __align__(16) __half g_Vth[BB * HH * DHH * LL];    // V fp16 [bh][dh][pos]
__device__ int g_cnt[BB];

// ---------- helpers ----------
__device__ __forceinline__ float ex2f(float x) {
    float y;
    asm("ex2.approx.ftz.f32 %0, %1;" : "=f"(y) : "f"(x));
    return y;
}
// Polynomial 2^x on the FMA/ALU pipes (MUFU offload). |x| <= ~16.
// Magic-constant round, degree-4 Taylor on f in [-0.5,0.5] (err <= 4.2e-5),
// exponent assembled via bit arithmetic. exp2poly(0) == 1.0 exactly.
__device__ __forceinline__ float exp2poly(float x) {
    const float MAGIC = 12582912.0f;  // 1.5 * 2^23
    const float t = x + MAGIC;
    const float n = t - MAGIC;
    const float f = x - n;
    float p = 0.00961812911f;
    p = fmaf(p, f, 0.0555041087f);
    p = fmaf(p, f, 0.240226507f);
    p = fmaf(p, f, 0.693147180f);
    p = fmaf(p, f, 1.0f);
    const uint32_t scale_bits =
        (uint32_t)((__float_as_int(t) + (127 - 0x4B400000)) << 23);
    return p * __uint_as_float(scale_bits);
}
__device__ __forceinline__ uint32_t h16pack(float hi, float lo) {  // f16x2
    uint32_t r;
    asm("cvt.rn.f16x2.f32 %0, %1, %2;" : "=r"(r) : "f"(hi), "f"(lo));
    return r;
}
// fp16 MMA m16n8k16
__device__ __forceinline__ void mma16816h(float* d, const uint32_t* a, uint32_t b0,
                                          uint32_t b1) {
    asm("mma.sync.aligned.m16n8k16.row.col.f32.f16.f16.f32 "
        "{%0,%1,%2,%3}, {%4,%5,%6,%7}, {%8,%9}, {%0,%1,%2,%3};"
        : "+f"(d[0]), "+f"(d[1]), "+f"(d[2]), "+f"(d[3])
        : "r"(a[0]), "r"(a[1]), "r"(a[2]), "r"(a[3]), "r"(b0), "r"(b1));
}
// cp.async 16B (zero-fills when srcsize=0)
__device__ __forceinline__ void cpasync16(uint32_t dst, const void* src, int srcsize) {
    asm volatile("cp.async.cg.shared.global [%0], [%1], 16, %2;" ::"r"(dst),
                 "l"(src), "r"(srcsize));
}
#define CP_COMMIT() asm volatile("cp.async.commit_group;" ::: "memory")
#define CP_WAIT0() asm volatile("cp.async.wait_group 0;" ::: "memory")

// ============================================================
// HMMA projection with FUSED mask scan + transpose (as R14).
// ============================================================
#define PSTR 36
#define XH_OFF (64 * 129)            // after fp32 chunk [64][129]
#define WH_OFF (XH_OFF + 128 * PSTR)
#define PROJ_WORDS (WH_OFF + 128 * PSTR)
#define PROJ_SMEM (PROJ_WORDS * 4)

__global__ __launch_bounds__(256, 3) void proj_kernel(
    const float* __restrict__ queries, const int* __restrict__ mask,
    const float* __restrict__ W_mem, const float* __restrict__ W_q) {
    extern __shared__ uint32_t ps[];
    float* sF = (float*)ps;          // [64][129]
    uint32_t* sXh = ps + XH_OFF;
    uint32_t* sWh = ps + WH_OFF;
    __shared__ int sPos[128];
    __shared__ int s_warp[8];
    __shared__ int s_total;

    const int tid = threadIdx.x;
    const int lane = tid & 31, wrp = tid >> 5;
    const int r = lane >> 2, cq = lane & 3;
    const int lgrp = wrp & 3, ehalf = wrp >> 2;
    const int lt = blockIdx.x & 15, b = blockIdx.x >> 4;
    const int et = blockIdx.y;
    const int l0 = lt * 128;
    const float* Wsrc = (et == 2) ? W_q : (W_mem + (size_t)et * 128 * DD);

    // ---- fused mask scan (full batch, redundant per CTA) ----
    {
        int m[8];
        int c = 0;
        const int lb = tid * 8;
#pragma unroll
        for (int i = 0; i < 8; i++) {
            m[i] = mask[b * LL + lb + i];
            c += m[i];
        }
        int incl = c;
#pragma unroll
        for (int off = 1; off < 32; off <<= 1) {
            int o = __shfl_up_sync(0xffffffffu, incl, off);
            if (lane >= off) incl += o;
        }
        if (lane == 31) s_warp[wrp] = incl;
        __syncthreads();
        if (tid == 0) {
            int acc = 0;
#pragma unroll
            for (int i = 0; i < 8; i++) {
                int t = s_warp[i];
                s_warp[i] = acc;
                acc += t;
            }
            s_total = acc;
        }
        __syncthreads();
        int pos = incl - c + s_warp[wrp];
        if ((tid >> 4) == lt) {          // this thread's 8 l's lie in our window
            const int base = lb - l0;
#pragma unroll
            for (int i = 0; i < 8; i++) {
                sPos[base + i] = m[i] ? pos : -1;
                pos += m[i];
            }
        }
        __syncthreads();
        const int nv = s_total;
        // lt==0 CTAs: zero pad rows [nv, nv8) and publish g_cnt
        if (lt == 0) {
            const int pad8 = ((nv + 7) & ~7) - nv;
            if (et == 0) {
                if (tid == 0) g_cnt[b] = nv;
                for (int x = tid; x < HH * pad8 * 8; x += 256) {
                    int wd = x & 7, t = x >> 3;
                    int rr = nv + t % pad8, h = t / pad8;
                    g_Khf[(((size_t)(b * HH + h)) * LL + rr) * 8 + wd] = 0u;
                }
            } else if (et == 1 && pad8 > 0) {
                for (int x = tid; x < HH * DHH * pad8; x += 256) {
                    int hd = x / pad8;
                    int rr = nv + x % pad8;
                    g_Vth[((size_t)b * HH * DHH + hd) * LL + rr] = __float2half(0.f);
                }
            }
        }
    }

    float C[2][8][4];
#pragma unroll
    for (int mt = 0; mt < 2; mt++)
#pragma unroll
        for (int n = 0; n < 8; n++)
#pragma unroll
            for (int k = 0; k < 4; k++) C[mt][n][k] = 0.f;

    for (int kc = 0; kc < 2; kc++) {
        __syncthreads();
        // load queries chunk [64 d][128 l] fp32 (coalesced over l)
#pragma unroll
        for (int i = 0; i < 8; i++) {
            const int idx = tid + i * 256;
            const int d = idx >> 5, lq = idx & 31;
            float4 v = *(const float4*)&queries[((size_t)b * DD + kc * 64 + d) * LL +
                                                l0 + lq * 4];
            float* p = &sF[d * 129 + lq * 4];
            p[0] = v.x; p[1] = v.y; p[2] = v.z; p[3] = v.w;
        }
        // W tile: fp32 -> single fp16
#pragma unroll
        for (int i = 0; i < 8; i++) {
            const int idx = tid + i * 256;
            const int e = idx >> 4, dq = idx & 15;
            float4 v = *(const float4*)&Wsrc[(size_t)e * DD + kc * 64 + dq * 4];
            *(uint2*)&sWh[e * PSTR + dq * 2] =
                make_uint2(h16pack(v.y, v.x), h16pack(v.w, v.z));
        }
        __syncthreads();
        // transpose+convert X chunk to single fp16
#pragma unroll
        for (int i = 0; i < 16; i++) {
            const int l = wrp * 16 + i;
            const float f0 = sF[(2 * lane) * 129 + l];
            const float f1 = sF[(2 * lane + 1) * 129 + l];
            sXh[l * PSTR + lane] = h16pack(f1, f0);
        }
        __syncthreads();

#pragma unroll
        for (int kch = 0; kch < 4; kch++) {
            uint32_t ah[2][4];
#pragma unroll
            for (int mt = 0; mt < 2; mt++)
#pragma unroll
                for (int k = 0; k < 4; k++) {
                    const int row = lgrp * 32 + mt * 16 + r + (k & 1) * 8;
                    const int wd = kch * 8 + cq + (k >> 1) * 4;
                    ah[mt][k] = sXh[row * PSTR + wd];
                }
#pragma unroll
            for (int n = 0; n < 8; n++) {
                const int er = ehalf * 64 + n * 8 + r;
                const uint32_t bh0 = sWh[er * PSTR + kch * 8 + cq];
                const uint32_t bh1 = sWh[er * PSTR + kch * 8 + cq + 4];
#pragma unroll
                for (int mt = 0; mt < 2; mt++)
                    mma16816h(C[mt][n], ah[mt], bh0, bh1);
            }
        }
    }

    // ---- epilogue ----
#pragma unroll
    for (int mt = 0; mt < 2; mt++) {
        const int r0 = lgrp * 32 + mt * 16 + r;
        const int r1 = r0 + 8;
#pragma unroll
        for (int n = 0; n < 8; n++) {
            const int e = ehalf * 64 + n * 8 + 2 * cq;
            const int h = e >> 4;
            const int wd = (e & 15) >> 1;
            const float c0 = C[mt][n][0], c1 = C[mt][n][1];
            const float c2 = C[mt][n][2], c3 = C[mt][n][3];
            if (et == 2) {  // Q: single fp16, scaled
                const size_t o0 = (((size_t)(b * HH + h)) * LL + l0 + r0) * 8 + wd;
                const size_t o1 = (((size_t)(b * HH + h)) * LL + l0 + r1) * 8 + wd;
                g_Qhf[o0] = h16pack(c1 * QSCALE, c0 * QSCALE);
                g_Qhf[o1] = h16pack(c3 * QSCALE, c2 * QSCALE);
            } else if (et == 0) {  // K: fp16, compacted
                const int p0 = sPos[r0], p1 = sPos[r1];
                if (p0 >= 0)
                    g_Khf[(((size_t)(b * HH + h)) * LL + p0) * 8 + wd] =
                        h16pack(c1, c0);
                if (p1 >= 0)
                    g_Khf[(((size_t)(b * HH + h)) * LL + p1) * 8 + wd] =
                        h16pack(c3, c2);
            } else {  // V: fp16 transposed, compacted
                const int p0 = sPos[r0], p1 = sPos[r1];
                const int dh = e & 15;
                const size_t base = ((size_t)(b * HH + h)) * DHH;
                if (p0 >= 0) {
                    g_Vth[(base + dh) * LL + p0] = __float2half_rn(c0);
                    g_Vth[(base + dh + 1) * LL + p0] = __float2half_rn(c1);
                }
                if (p1 >= 0) {
                    g_Vth[(base + dh) * LL + p1] = __float2half_rn(c2);
                    g_Vth[(base + dh + 1) * LL + p1] = __float2half_rn(c3);
                }
            }
        }
    }
}

// ============================================================
// fp16 HMMA flash attention: as R14, with the softmax exp2
// stream split across pipes (n=0 -> MUFU ex2, n=1 -> FMA poly).
// Grid (8, 64) = 512 CTAs, block 128, 4 CTAs/SM = one wave.
// ============================================================
#define KT 128
#define KSTR 12   // K row: 8 data words + 4 pad (conflict-free B-frags)
#define VSTR 68   // V row: 64 data words + 4 pad (conflict-free B-frags)

__global__ __launch_bounds__(128, 4) void attn_kernel(float* __restrict__ out) {
    __shared__ uint32_t sKf[2][KT * KSTR];
    __shared__ uint32_t sVf[2][16 * VSTR];

    const int tid = threadIdx.x;
    const int lane = tid & 31, w = tid >> 5;
    const int r = lane >> 2, cq = lane & 3;
    const int bh = blockIdx.y, b = bh >> 3, hd = bh & 7;
    const int q0 = blockIdx.x * 256;

    const int nv = g_cnt[b];
    const int nv8 = (nv + 7) & ~7;
    const int nt = (nv + KT - 1) / KT;

    // Q A-fragments (single fp16) for both halves
    uint32_t qh[2][2][4];
#pragma unroll
    for (int hf = 0; hf < 2; hf++)
#pragma unroll
        for (int mt = 0; mt < 2; mt++) {
            const int row = q0 + hf * 128 + w * 32 + mt * 16 + r;
#pragma unroll
            for (int k = 0; k < 4; k++) {
                const int rr = row + (k & 1) * 8;
                const int wd = cq + (k >> 1) * 4;
                qh[hf][mt][k] = g_Qhf[((size_t)bh * LL + rr) * 8 + wd];
            }
        }

    // cp.async per-thread constants
    const uint32_t aK = (uint32_t)__cvta_generic_to_shared(sKf);
    const uint32_t aV = (uint32_t)__cvta_generic_to_shared(sVf);
    const int vdh = tid >> 3, vch = tid & 7;
    const uint32_t koff = (uint32_t)(tid * KSTR) * 4;
    const uint32_t voff = (uint32_t)(vdh * VSTR + vch * 8) * 4;
    const uint32_t kbufsz = KT * KSTR * 4, vbufsz = 16 * VSTR * 4;

    auto issue = [&](int bi, int k0) {
        const int ksz = (k0 + tid < nv8) ? 16 : 0;
        const size_t ko = ((size_t)bh * LL + k0 + tid) * 8;
        cpasync16(aK + bi * kbufsz + koff, &g_Khf[ko], ksz);
        cpasync16(aK + bi * kbufsz + koff + 16, &g_Khf[ko + 4], ksz);
        const __half* vsrc = &g_Vth[((size_t)bh * DHH + vdh) * LL + k0 + vch * 16];
        cpasync16(aV + bi * vbufsz + voff, vsrc,
                  (k0 + vch * 16 < nv8) ? 16 : 0);
        cpasync16(aV + bi * vbufsz + voff + 16, vsrc + 8,
                  (k0 + vch * 16 + 8 < nv8) ? 16 : 0);
    };

    float O[2][2][2][4];  // [half][mt][n]
#pragma unroll
    for (int hf = 0; hf < 2; hf++)
#pragma unroll
        for (int mt = 0; mt < 2; mt++)
#pragma unroll
            for (int n = 0; n < 2; n++)
#pragma unroll
                for (int k = 0; k < 4; k++) O[hf][mt][n][k] = 0.f;
    float rs[2][2][2] = {};  // [half][mt][row half]

    issue(0, 0);
    CP_COMMIT();

    for (int t = 0; t < nt; t++) {
        CP_WAIT0();
        __syncthreads();
        if (t + 1 < nt) issue((t + 1) & 1, (t + 1) * KT);
        CP_COMMIT();

        const uint32_t* Kf = sKf[t & 1];
        const uint32_t* Vf = sVf[t & 1];

#pragma unroll
        for (int s = 0; s < 8; s++) {   // 16-key chunks
#pragma unroll
            for (int hf = 0; hf < 2; hf++) {
                float S[2][2][4];
#pragma unroll
                for (int mt = 0; mt < 2; mt++)
#pragma unroll
                    for (int n = 0; n < 2; n++)
#pragma unroll
                        for (int k = 0; k < 4; k++) S[mt][n][k] = 0.f;

#pragma unroll
                for (int n = 0; n < 2; n++) {
                    const int kw = (s * 16 + n * 8 + r) * KSTR + cq;
                    const uint32_t k0w = Kf[kw], k1w = Kf[kw + 4];
#pragma unroll
                    for (int mt = 0; mt < 2; mt++)
                        mma16816h(S[mt][n], qh[hf][mt], k0w, k1w);
                }

                uint32_t ph[2][4];
#pragma unroll
                for (int mt = 0; mt < 2; mt++) {
                    float p[2][4];
                    // n=0 half: MUFU ex2; n=1 half: poly on FMA/ALU pipes
#pragma unroll
                    for (int k = 0; k < 4; k++)
                        p[0][k] = ex2f(S[mt][0][k]);
#pragma unroll
                    for (int k = 0; k < 4; k++)
                        p[1][k] = exp2poly(S[mt][1][k]);
                    rs[hf][mt][0] += (p[0][0] + p[0][1]) + (p[1][0] + p[1][1]);
                    rs[hf][mt][1] += (p[0][2] + p[0][3]) + (p[1][2] + p[1][3]);
                    ph[mt][0] = h16pack(p[0][1], p[0][0]);
                    ph[mt][1] = h16pack(p[0][3], p[0][2]);
                    ph[mt][2] = h16pack(p[1][1], p[1][0]);
                    ph[mt][3] = h16pack(p[1][3], p[1][2]);
                }

#pragma unroll
                for (int n = 0; n < 2; n++) {
                    const int vw = (n * 8 + r) * VSTR + s * 8 + cq;
                    const uint32_t v0 = Vf[vw], v1 = Vf[vw + 4];
#pragma unroll
                    for (int mt = 0; mt < 2; mt++)
                        mma16816h(O[hf][mt][n], ph[mt], v0, v1);
                }
            }
        }
    }

    // pads: zero K rows -> S=0 -> p=1 exactly on both exp paths
    const float pad = (float)(nt * KT - nv);
#pragma unroll
    for (int hf = 0; hf < 2; hf++) {
        float inv[2][2];
#pragma unroll
        for (int mt = 0; mt < 2; mt++)
#pragma unroll
            for (int rh = 0; rh < 2; rh++) {
                float v = rs[hf][mt][rh];
                v += __shfl_xor_sync(0xffffffffu, v, 1);
                v += __shfl_xor_sync(0xffffffffu, v, 2);
                inv[mt][rh] = 1.f / (v - pad);
            }
#pragma unroll
        for (int mt = 0; mt < 2; mt++) {
            const int q = q0 + hf * 128 + w * 32 + mt * 16 + r;
#pragma unroll
            for (int n = 0; n < 2; n++) {
                const int dh = hd * DHH + n * 8 + cq * 2;
                out[((size_t)b * DD + dh) * LL + q] = O[hf][mt][n][0] * inv[mt][0];
                out[((size_t)b * DD + dh + 1) * LL + q] = O[hf][mt][n][1] * inv[mt][0];
                out[((size_t)b * DD + dh) * LL + q + 8] = O[hf][mt][n][2] * inv[mt][1];
                out[((size_t)b * DD + dh + 1) * LL + q + 8] =
                    O[hf][mt][n][3] * inv[mt][1];
            }
        }
    }
}

extern "C" void kernel_launch(void* const* d_in, const int* in_sizes, int n_in,
                              void* d_out, int out_size) {
    const float* queries = (const float*)d_in[0];
    const int* mask = (const int*)d_in[1];
    const float* W_mem = (const float*)d_in[2];
    const float* W_q = (const float*)d_in[3];
    float* out = (float*)d_out;

    cudaFuncSetAttribute(proj_kernel, cudaFuncAttributeMaxDynamicSharedMemorySize,
                         PROJ_SMEM);
    proj_kernel<<<dim3(16 * BB, 3), 256, PROJ_SMEM>>>(queries, mask, W_mem, W_q);
    attn_kernel<<<dim3(LL / 256, BB * HH), 128>>>(out);
}

// round 16
// speedup vs baseline: 1.9775x; 1.9775x over previous
#include <cuda_runtime.h>
#include <cuda_bf16.h>
#include <cuda_fp16.h>
#include <cstdint>

#define BB 8
#define DD 128
#define LL 2048
#define HH 8
#define DHH 16
#define QSCALE 0.3606737602222409f  // DH^-0.5 * log2(e)

// Scratch
__device__ __align__(16) uint32_t g_Qhf[BB * HH * LL * 8];    // Q fp16 [bh][l][dh/2]
__device__ __align__(16) uint32_t g_Khf[BB * HH * LL * 8];    // K fp16 [bh][pos][dh/2]
__device__ __align__(16) __half g_Vth[BB * HH * DHH * LL];    // V fp16 [bh][dh][pos]
__device__ int g_cnt[BB];

// ---------- helpers ----------
__device__ __forceinline__ float ex2f(float x) {
    float y;
    asm("ex2.approx.ftz.f32 %0, %1;" : "=f"(y) : "f"(x));
    return y;
}
__device__ __forceinline__ uint32_t h16pack(float hi, float lo) {  // f16x2
    uint32_t r;
    asm("cvt.rn.f16x2.f32 %0, %1, %2;" : "=r"(r) : "f"(hi), "f"(lo));
    return r;
}
// fp16 MMA m16n8k16
__device__ __forceinline__ void mma16816h(float* d, const uint32_t* a, uint32_t b0,
                                          uint32_t b1) {
    asm("mma.sync.aligned.m16n8k16.row.col.f32.f16.f16.f32 "
        "{%0,%1,%2,%3}, {%4,%5,%6,%7}, {%8,%9}, {%0,%1,%2,%3};"
        : "+f"(d[0]), "+f"(d[1]), "+f"(d[2]), "+f"(d[3])
        : "r"(a[0]), "r"(a[1]), "r"(a[2]), "r"(a[3]), "r"(b0), "r"(b1));
}
// cp.async 16B (zero-fills when srcsize=0)
__device__ __forceinline__ void cpasync16(uint32_t dst, const void* src, int srcsize) {
    asm volatile("cp.async.cg.shared.global [%0], [%1], 16, %2;" ::"r"(dst),
                 "l"(src), "r"(srcsize));
}
#define CP_COMMIT() asm volatile("cp.async.commit_group;" ::: "memory")
#define CP_WAIT0() asm volatile("cp.async.wait_group 0;" ::: "memory")

// ============================================================
// HMMA projection with FUSED mask scan + transpose (as R14).
// ============================================================
#define PSTR 36
#define XH_OFF (64 * 129)            // after fp32 chunk [64][129]
#define WH_OFF (XH_OFF + 128 * PSTR)
#define PROJ_WORDS (WH_OFF + 128 * PSTR)
#define PROJ_SMEM (PROJ_WORDS * 4)

__global__ __launch_bounds__(256, 3) void proj_kernel(
    const float* __restrict__ queries, const int* __restrict__ mask,
    const float* __restrict__ W_mem, const float* __restrict__ W_q) {
    extern __shared__ uint32_t ps[];
    float* sF = (float*)ps;          // [64][129]
    uint32_t* sXh = ps + XH_OFF;
    uint32_t* sWh = ps + WH_OFF;
    __shared__ int sPos[128];
    __shared__ int s_warp[8];
    __shared__ int s_total;

    const int tid = threadIdx.x;
    const int lane = tid & 31, wrp = tid >> 5;
    const int r = lane >> 2, cq = lane & 3;
    const int lgrp = wrp & 3, ehalf = wrp >> 2;
    const int lt = blockIdx.x & 15, b = blockIdx.x >> 4;
    const int et = blockIdx.y;
    const int l0 = lt * 128;
    const float* Wsrc = (et == 2) ? W_q : (W_mem + (size_t)et * 128 * DD);

    // ---- fused mask scan (full batch, redundant per CTA) ----
    {
        int m[8];
        int c = 0;
        const int lb = tid * 8;
#pragma unroll
        for (int i = 0; i < 8; i++) {
            m[i] = mask[b * LL + lb + i];
            c += m[i];
        }
        int incl = c;
#pragma unroll
        for (int off = 1; off < 32; off <<= 1) {
            int o = __shfl_up_sync(0xffffffffu, incl, off);
            if (lane >= off) incl += o;
        }
        if (lane == 31) s_warp[wrp] = incl;
        __syncthreads();
        if (tid == 0) {
            int acc = 0;
#pragma unroll
            for (int i = 0; i < 8; i++) {
                int t = s_warp[i];
                s_warp[i] = acc;
                acc += t;
            }
            s_total = acc;
        }
        __syncthreads();
        int pos = incl - c + s_warp[wrp];
        if ((tid >> 4) == lt) {          // this thread's 8 l's lie in our window
            const int base = lb - l0;
#pragma unroll
            for (int i = 0; i < 8; i++) {
                sPos[base + i] = m[i] ? pos : -1;
                pos += m[i];
            }
        }
        __syncthreads();
        const int nv = s_total;
        // lt==0 CTAs: zero pad rows [nv, nv8) and publish g_cnt
        if (lt == 0) {
            const int pad8 = ((nv + 7) & ~7) - nv;
            if (et == 0) {
                if (tid == 0) g_cnt[b] = nv;
                for (int x = tid; x < HH * pad8 * 8; x += 256) {
                    int wd = x & 7, t = x >> 3;
                    int rr = nv + t % pad8, h = t / pad8;
                    g_Khf[(((size_t)(b * HH + h)) * LL + rr) * 8 + wd] = 0u;
                }
            } else if (et == 1 && pad8 > 0) {
                for (int x = tid; x < HH * DHH * pad8; x += 256) {
                    int hd = x / pad8;
                    int rr = nv + x % pad8;
                    g_Vth[((size_t)b * HH * DHH + hd) * LL + rr] = __float2half(0.f);
                }
            }
        }
    }

    float C[2][8][4];
#pragma unroll
    for (int mt = 0; mt < 2; mt++)
#pragma unroll
        for (int n = 0; n < 8; n++)
#pragma unroll
            for (int k = 0; k < 4; k++) C[mt][n][k] = 0.f;

    for (int kc = 0; kc < 2; kc++) {
        __syncthreads();
        // load queries chunk [64 d][128 l] fp32 (coalesced over l)
#pragma unroll
        for (int i = 0; i < 8; i++) {
            const int idx = tid + i * 256;
            const int d = idx >> 5, lq = idx & 31;
            float4 v = *(const float4*)&queries[((size_t)b * DD + kc * 64 + d) * LL +
                                                l0 + lq * 4];
            float* p = &sF[d * 129 + lq * 4];
            p[0] = v.x; p[1] = v.y; p[2] = v.z; p[3] = v.w;
        }
        // W tile: fp32 -> single fp16
#pragma unroll
        for (int i = 0; i < 8; i++) {
            const int idx = tid + i * 256;
            const int e = idx >> 4, dq = idx & 15;
            float4 v = *(const float4*)&Wsrc[(size_t)e * DD + kc * 64 + dq * 4];
            *(uint2*)&sWh[e * PSTR + dq * 2] =
                make_uint2(h16pack(v.y, v.x), h16pack(v.w, v.z));
        }
        __syncthreads();
        // transpose+convert X chunk to single fp16
#pragma unroll
        for (int i = 0; i < 16; i++) {
            const int l = wrp * 16 + i;
            const float f0 = sF[(2 * lane) * 129 + l];
            const float f1 = sF[(2 * lane + 1) * 129 + l];
            sXh[l * PSTR + lane] = h16pack(f1, f0);
        }
        __syncthreads();

#pragma unroll
        for (int kch = 0; kch < 4; kch++) {
            uint32_t ah[2][4];
#pragma unroll
            for (int mt = 0; mt < 2; mt++)
#pragma unroll
                for (int k = 0; k < 4; k++) {
                    const int row = lgrp * 32 + mt * 16 + r + (k & 1) * 8;
                    const int wd = kch * 8 + cq + (k >> 1) * 4;
                    ah[mt][k] = sXh[row * PSTR + wd];
                }
#pragma unroll
            for (int n = 0; n < 8; n++) {
                const int er = ehalf * 64 + n * 8 + r;
                const uint32_t bh0 = sWh[er * PSTR + kch * 8 + cq];
                const uint32_t bh1 = sWh[er * PSTR + kch * 8 + cq + 4];
#pragma unroll
                for (int mt = 0; mt < 2; mt++)
                    mma16816h(C[mt][n], ah[mt], bh0, bh1);
            }
        }
    }

    // ---- epilogue ----
#pragma unroll
    for (int mt = 0; mt < 2; mt++) {
        const int r0 = lgrp * 32 + mt * 16 + r;
        const int r1 = r0 + 8;
#pragma unroll
        for (int n = 0; n < 8; n++) {
            const int e = ehalf * 64 + n * 8 + 2 * cq;
            const int h = e >> 4;
            const int wd = (e & 15) >> 1;
            const float c0 = C[mt][n][0], c1 = C[mt][n][1];
            const float c2 = C[mt][n][2], c3 = C[mt][n][3];
            if (et == 2) {  // Q: single fp16, scaled
                const size_t o0 = (((size_t)(b * HH + h)) * LL + l0 + r0) * 8 + wd;
                const size_t o1 = (((size_t)(b * HH + h)) * LL + l0 + r1) * 8 + wd;
                g_Qhf[o0] = h16pack(c1 * QSCALE, c0 * QSCALE);
                g_Qhf[o1] = h16pack(c3 * QSCALE, c2 * QSCALE);
            } else if (et == 0) {  // K: fp16, compacted
                const int p0 = sPos[r0], p1 = sPos[r1];
                if (p0 >= 0)
                    g_Khf[(((size_t)(b * HH + h)) * LL + p0) * 8 + wd] =
                        h16pack(c1, c0);
                if (p1 >= 0)
                    g_Khf[(((size_t)(b * HH + h)) * LL + p1) * 8 + wd] =
                        h16pack(c3, c2);
            } else {  // V: fp16 transposed, compacted
                const int p0 = sPos[r0], p1 = sPos[r1];
                const int dh = e & 15;
                const size_t base = ((size_t)(b * HH + h)) * DHH;
                if (p0 >= 0) {
                    g_Vth[(base + dh) * LL + p0] = __float2half_rn(c0);
                    g_Vth[(base + dh + 1) * LL + p0] = __float2half_rn(c1);
                }
                if (p1 >= 0) {
                    g_Vth[(base + dh) * LL + p1] = __float2half_rn(c2);
                    g_Vth[(base + dh + 1) * LL + p1] = __float2half_rn(c3);
                }
            }
        }
    }
}

// ============================================================
// fp16 HMMA flash attention: 512 queries/CTA, 256 threads
// (2 warp-groups x 4 warps; each group runs the R14 per-256-q
// path on its own window, sharing the K/V smem pipeline).
// Key tiles of 128, cp.async double-buffered (nv8 predicates),
// shift-free softmax (p = ex2(S), pads contribute exactly 1).
// Grid (4, 64) = 256 CTAs, 2 CTAs/SM -> single wave, 16 w/SM.
// ============================================================
#define KT 128
#define KSTR 12   // K row: 8 data words + 4 pad (conflict-free B-frags)
#define VSTR 68   // V row: 64 data words + 4 pad (conflict-free B-frags)

__global__ __launch_bounds__(256, 2) void attn_kernel(float* __restrict__ out) {
    __shared__ uint32_t sKf[2][KT * KSTR];
    __shared__ uint32_t sVf[2][16 * VSTR];

    const int tid = threadIdx.x;
    const int wg = tid >> 7;              // warp-group 0/1
    const int wtid = tid & 127;
    const int lane = tid & 31, w = (wtid >> 5);
    const int r = lane >> 2, cq = lane & 3;
    const int bh = blockIdx.y, b = bh >> 3, hd = bh & 7;
    const int q0 = blockIdx.x * 512 + wg * 256;

    const int nv = g_cnt[b];
    const int nv8 = (nv + 7) & ~7;
    const int nt = (nv + KT - 1) / KT;

    // Q A-fragments (single fp16) for both halves of this group's window
    uint32_t qh[2][2][4];
#pragma unroll
    for (int hf = 0; hf < 2; hf++)
#pragma unroll
        for (int mt = 0; mt < 2; mt++) {
            const int row = q0 + hf * 128 + w * 32 + mt * 16 + r;
#pragma unroll
            for (int k = 0; k < 4; k++) {
                const int rr = row + (k & 1) * 8;
                const int wd = cq + (k >> 1) * 4;
                qh[hf][mt][k] = g_Qhf[((size_t)bh * LL + rr) * 8 + wd];
            }
        }

    // cp.async per-thread constants (256 threads: 1 K + 1 V copy each)
    const uint32_t aK = (uint32_t)__cvta_generic_to_shared(sKf);
    const uint32_t aV = (uint32_t)__cvta_generic_to_shared(sVf);
    const int krow = tid >> 1, kpart = tid & 1;
    const int vdh = tid >> 4, vrest = tid & 15;
    const int vch = vrest >> 1, vpart = vrest & 1;
    const uint32_t koff = (uint32_t)(krow * KSTR) * 4 + kpart * 16;
    const uint32_t voff = (uint32_t)(vdh * VSTR + vch * 8) * 4 + vpart * 16;
    const uint32_t kbufsz = KT * KSTR * 4, vbufsz = 16 * VSTR * 4;

    auto issue = [&](int bi, int k0) {
        const int ksz = (k0 + krow < nv8) ? 16 : 0;
        cpasync16(aK + bi * kbufsz + koff,
                  &g_Khf[((size_t)bh * LL + k0 + krow) * 8 + kpart * 4], ksz);
        const int vsz = (k0 + vch * 16 + vpart * 8 < nv8) ? 16 : 0;
        cpasync16(aV + bi * vbufsz + voff,
                  &g_Vth[((size_t)bh * DHH + vdh) * LL + k0 + vch * 16 + vpart * 8],
                  vsz);
    };

    float O[2][2][2][4];  // [half][mt][n]
#pragma unroll
    for (int hf = 0; hf < 2; hf++)
#pragma unroll
        for (int mt = 0; mt < 2; mt++)
#pragma unroll
            for (int n = 0; n < 2; n++)
#pragma unroll
                for (int k = 0; k < 4; k++) O[hf][mt][n][k] = 0.f;
    float rs[2][2][2] = {};  // [half][mt][row half]

    issue(0, 0);
    CP_COMMIT();

    for (int t = 0; t < nt; t++) {
        CP_WAIT0();
        __syncthreads();
        if (t + 1 < nt) issue((t + 1) & 1, (t + 1) * KT);
        CP_COMMIT();

        const uint32_t* Kf = sKf[t & 1];
        const uint32_t* Vf = sVf[t & 1];

#pragma unroll
        for (int s = 0; s < 8; s++) {   // 16-key chunks
#pragma unroll
            for (int hf = 0; hf < 2; hf++) {
                float S[2][2][4];
#pragma unroll
                for (int mt = 0; mt < 2; mt++)
#pragma unroll
                    for (int n = 0; n < 2; n++)
#pragma unroll
                        for (int k = 0; k < 4; k++) S[mt][n][k] = 0.f;

#pragma unroll
                for (int n = 0; n < 2; n++) {
                    const int kw = (s * 16 + n * 8 + r) * KSTR + cq;
                    const uint32_t k0w = Kf[kw], k1w = Kf[kw + 4];
#pragma unroll
                    for (int mt = 0; mt < 2; mt++)
                        mma16816h(S[mt][n], qh[hf][mt], k0w, k1w);
                }

                uint32_t ph[2][4];
#pragma unroll
                for (int mt = 0; mt < 2; mt++) {
                    float p[2][4];
#pragma unroll
                    for (int n = 0; n < 2; n++) {
#pragma unroll
                        for (int k = 0; k < 4; k++)
                            p[n][k] = ex2f(S[mt][n][k]);   // shift-free
                        rs[hf][mt][0] += p[n][0] + p[n][1];
                        rs[hf][mt][1] += p[n][2] + p[n][3];
                    }
                    ph[mt][0] = h16pack(p[0][1], p[0][0]);
                    ph[mt][1] = h16pack(p[0][3], p[0][2]);
                    ph[mt][2] = h16pack(p[1][1], p[1][0]);
                    ph[mt][3] = h16pack(p[1][3], p[1][2]);
                }

#pragma unroll
                for (int n = 0; n < 2; n++) {
                    const int vw = (n * 8 + r) * VSTR + s * 8 + cq;
                    const uint32_t v0 = Vf[vw], v1 = Vf[vw + 4];
#pragma unroll
                    for (int mt = 0; mt < 2; mt++)
                        mma16816h(O[hf][mt][n], ph[mt], v0, v1);
                }
            }
        }
    }

    // pads: zero K rows -> S=0 -> p=1 each; subtract exactly
    const float pad = (float)(nt * KT - nv);
#pragma unroll
    for (int hf = 0; hf < 2; hf++) {
        float inv[2][2];
#pragma unroll
        for (int mt = 0; mt < 2; mt++)
#pragma unroll
            for (int rh = 0; rh < 2; rh++) {
                float v = rs[hf][mt][rh];
                v += __shfl_xor_sync(0xffffffffu, v, 1);
                v += __shfl_xor_sync(0xffffffffu, v, 2);
                inv[mt][rh] = 1.f / (v - pad);
            }
#pragma unroll
        for (int mt = 0; mt < 2; mt++) {
            const int q = q0 + hf * 128 + w * 32 + mt * 16 + r;
#pragma unroll
            for (int n = 0; n < 2; n++) {
                const int dh = hd * DHH + n * 8 + cq * 2;
                out[((size_t)b * DD + dh) * LL + q] = O[hf][mt][n][0] * inv[mt][0];
                out[((size_t)b * DD + dh + 1) * LL + q] = O[hf][mt][n][1] * inv[mt][0];
                out[((size_t)b * DD + dh) * LL + q + 8] = O[hf][mt][n][2] * inv[mt][1];
                out[((size_t)b * DD + dh + 1) * LL + q + 8] =
                    O[hf][mt][n][3] * inv[mt][1];
            }
        }
    }
}

extern "C" void kernel_launch(void* const* d_in, const int* in_sizes, int n_in,
                              void* d_out, int out_size) {
    const float* queries = (const float*)d_in[0];
    const int* mask = (const int*)d_in[1];
    const float* W_mem = (const float*)d_in[2];
    const float* W_q = (const float*)d_in[3];
    float* out = (float*)d_out;

    cudaFuncSetAttribute(proj_kernel, cudaFuncAttributeMaxDynamicSharedMemorySize,
                         PROJ_SMEM);
    proj_kernel<<<dim3(16 * BB, 3), 256, PROJ_SMEM>>>(queries, mask, W_mem, W_q);
    attn_kernel<<<dim3(LL / 512, BB * HH), 256>>>(out);
}

// round 17
// speedup vs baseline: 2.1611x; 1.0928x over previous
#include <cuda_runtime.h>
#include <cuda_bf16.h>
#include <cuda_fp16.h>
#include <cstdint>

#define BB 8
#define DD 128
#define LL 2048
#define HH 8
#define DHH 16
#define QSCALE 0.3606737602222409f  // DH^-0.5 * log2(e)

// Scratch
__device__ __align__(16) uint32_t g_Qhf[BB * HH * LL * 8];    // Q fp16 [bh][l][dh/2]
__device__ __align__(16) uint32_t g_Khf[BB * HH * LL * 8];    // K fp16 [bh][pos][dh/2]
__device__ __align__(16) __half g_Vth[BB * HH * DHH * LL];    // V fp16 [bh][dh][pos]
__device__ int g_cnt[BB];

// ---------- helpers ----------
__device__ __forceinline__ float ex2f(float x) {
    float y;
    asm("ex2.approx.ftz.f32 %0, %1;" : "=f"(y) : "f"(x));
    return y;
}
__device__ __forceinline__ uint32_t h16pack(float hi, float lo) {  // f16x2
    uint32_t r;
    asm("cvt.rn.f16x2.f32 %0, %1, %2;" : "=r"(r) : "f"(hi), "f"(lo));
    return r;
}
// fp16 MMA m16n8k16
__device__ __forceinline__ void mma16816h(float* d, const uint32_t* a, uint32_t b0,
                                          uint32_t b1) {
    asm("mma.sync.aligned.m16n8k16.row.col.f32.f16.f16.f32 "
        "{%0,%1,%2,%3}, {%4,%5,%6,%7}, {%8,%9}, {%0,%1,%2,%3};"
        : "+f"(d[0]), "+f"(d[1]), "+f"(d[2]), "+f"(d[3])
        : "r"(a[0]), "r"(a[1]), "r"(a[2]), "r"(a[3]), "r"(b0), "r"(b1));
}
// cp.async 16B (zero-fills when srcsize=0)
__device__ __forceinline__ void cpasync16(uint32_t dst, const void* src, int srcsize) {
    asm volatile("cp.async.cg.shared.global [%0], [%1], 16, %2;" ::"r"(dst),
                 "l"(src), "r"(srcsize));
}
#define CP_COMMIT() asm volatile("cp.async.commit_group;" ::: "memory")
#define CP_WAIT0() asm volatile("cp.async.wait_group 0;" ::: "memory")

// ============================================================
// HMMA projection v2: ONE CTA per l-tile, internal et loop.
// Mask scan once; X loaded + transposed + converted ONCE into
// persistent smem; W staging overlays the dead fp32 buffer.
// et 0 -> K (fp16, compacted), 1 -> V (fp16, transposed,
// compacted), 2 -> Q (fp16, *QSCALE).
// Grid (16*B) = 128 CTAs, block 256.
// ============================================================
#define WSTR 36
#define XSTR2 68                       // X row stride: 64 data + 4 pad words
#define XH2_OFF (64 * 129)             // X fp16 region after fp32 staging
#define PROJ_WORDS (XH2_OFF + 128 * XSTR2)
#define PROJ_SMEM (PROJ_WORDS * 4)

__global__ __launch_bounds__(256, 2) void proj_kernel(
    const float* __restrict__ queries, const int* __restrict__ mask,
    const float* __restrict__ W_mem, const float* __restrict__ W_q) {
    extern __shared__ uint32_t ps[];
    float* sF = (float*)ps;            // [64][129] fp32 staging (dead after xpose)
    uint32_t* sWh = ps;                // W fp16 [128][WSTR] overlays sF
    uint32_t* sXh = ps + XH2_OFF;      // X fp16 [128 l][XSTR2] persistent
    __shared__ int sPos[128];
    __shared__ int s_warp[8];
    __shared__ int s_total;

    const int tid = threadIdx.x;
    const int lane = tid & 31, wrp = tid >> 5;
    const int r = lane >> 2, cq = lane & 3;
    const int lgrp = wrp & 3, ehalf = wrp >> 2;
    const int lt = blockIdx.x & 15, b = blockIdx.x >> 4;
    const int l0 = lt * 128;

    // ---- mask scan (full batch, once per CTA) ----
    {
        int m[8];
        int c = 0;
        const int lb = tid * 8;
#pragma unroll
        for (int i = 0; i < 8; i++) {
            m[i] = mask[b * LL + lb + i];
            c += m[i];
        }
        int incl = c;
#pragma unroll
        for (int off = 1; off < 32; off <<= 1) {
            int o = __shfl_up_sync(0xffffffffu, incl, off);
            if (lane >= off) incl += o;
        }
        if (lane == 31) s_warp[wrp] = incl;
        __syncthreads();
        if (tid == 0) {
            int acc = 0;
#pragma unroll
            for (int i = 0; i < 8; i++) {
                int t = s_warp[i];
                s_warp[i] = acc;
                acc += t;
            }
            s_total = acc;
        }
        __syncthreads();
        int pos = incl - c + s_warp[wrp];
        if ((tid >> 4) == lt) {          // this thread's 8 l's lie in our window
            const int base = lb - l0;
#pragma unroll
            for (int i = 0; i < 8; i++) {
                sPos[base + i] = m[i] ? pos : -1;
                pos += m[i];
            }
        }
        __syncthreads();
        const int nv = s_total;
        // lt==0 CTA: zero K and V pad rows [nv, nv8), publish g_cnt
        if (lt == 0) {
            const int pad8 = ((nv + 7) & ~7) - nv;
            if (tid == 0) g_cnt[b] = nv;
            if (pad8 > 0) {
                for (int x = tid; x < HH * pad8 * 8; x += 256) {
                    int wd = x & 7, t = x >> 3;
                    int rr = nv + t % pad8, h = t / pad8;
                    g_Khf[(((size_t)(b * HH + h)) * LL + rr) * 8 + wd] = 0u;
                }
                for (int x = tid; x < HH * DHH * pad8; x += 256) {
                    int hd = x / pad8;
                    int rr = nv + x % pad8;
                    g_Vth[((size_t)b * HH * DHH + hd) * LL + rr] = __float2half(0.f);
                }
            }
        }
    }

    // ---- load + transpose + convert X ONCE (both 64-d chunks) ----
    for (int kc = 0; kc < 2; kc++) {
        __syncthreads();
#pragma unroll
        for (int i = 0; i < 8; i++) {
            const int idx = tid + i * 256;
            const int d = idx >> 5, lq = idx & 31;
            float4 v = *(const float4*)&queries[((size_t)b * DD + kc * 64 + d) * LL +
                                                l0 + lq * 4];
            float* p = &sF[d * 129 + lq * 4];
            p[0] = v.x; p[1] = v.y; p[2] = v.z; p[3] = v.w;
        }
        __syncthreads();
#pragma unroll
        for (int i = 0; i < 16; i++) {
            const int l = wrp * 16 + i;
            const float f0 = sF[(2 * lane) * 129 + l];
            const float f1 = sF[(2 * lane + 1) * 129 + l];
            sXh[l * XSTR2 + kc * 32 + lane] = h16pack(f1, f0);
        }
    }

    // ---- et loop: K, V, Q share the loaded X ----
    for (int et = 0; et < 3; et++) {
        const float* Wsrc = (et == 2) ? W_q : (W_mem + (size_t)et * 128 * DD);

        float C[2][8][4];
#pragma unroll
        for (int mt = 0; mt < 2; mt++)
#pragma unroll
            for (int n = 0; n < 8; n++)
#pragma unroll
                for (int k = 0; k < 4; k++) C[mt][n][k] = 0.f;

        for (int kc = 0; kc < 2; kc++) {
            __syncthreads();   // prior readers of sWh done
#pragma unroll
            for (int i = 0; i < 8; i++) {
                const int idx = tid + i * 256;
                const int e = idx >> 4, dq = idx & 15;
                float4 v = *(const float4*)&Wsrc[(size_t)e * DD + kc * 64 + dq * 4];
                *(uint2*)&sWh[e * WSTR + dq * 2] =
                    make_uint2(h16pack(v.y, v.x), h16pack(v.w, v.z));
            }
            __syncthreads();

#pragma unroll
            for (int kch = 0; kch < 4; kch++) {
                uint32_t ah[2][4];
#pragma unroll
                for (int mt = 0; mt < 2; mt++)
#pragma unroll
                    for (int k = 0; k < 4; k++) {
                        const int row = lgrp * 32 + mt * 16 + r + (k & 1) * 8;
                        const int wd = kc * 32 + kch * 8 + cq + (k >> 1) * 4;
                        ah[mt][k] = sXh[row * XSTR2 + wd];
                    }
#pragma unroll
                for (int n = 0; n < 8; n++) {
                    const int er = ehalf * 64 + n * 8 + r;
                    const uint32_t bh0 = sWh[er * WSTR + kch * 8 + cq];
                    const uint32_t bh1 = sWh[er * WSTR + kch * 8 + cq + 4];
#pragma unroll
                    for (int mt = 0; mt < 2; mt++)
                        mma16816h(C[mt][n], ah[mt], bh0, bh1);
                }
            }
        }

        // ---- epilogue for this et ----
#pragma unroll
        for (int mt = 0; mt < 2; mt++) {
            const int r0 = lgrp * 32 + mt * 16 + r;
            const int r1 = r0 + 8;
#pragma unroll
            for (int n = 0; n < 8; n++) {
                const int e = ehalf * 64 + n * 8 + 2 * cq;
                const int h = e >> 4;
                const int wd = (e & 15) >> 1;
                const float c0 = C[mt][n][0], c1 = C[mt][n][1];
                const float c2 = C[mt][n][2], c3 = C[mt][n][3];
                if (et == 2) {  // Q: single fp16, scaled
                    const size_t o0 = (((size_t)(b * HH + h)) * LL + l0 + r0) * 8 + wd;
                    const size_t o1 = (((size_t)(b * HH + h)) * LL + l0 + r1) * 8 + wd;
                    g_Qhf[o0] = h16pack(c1 * QSCALE, c0 * QSCALE);
                    g_Qhf[o1] = h16pack(c3 * QSCALE, c2 * QSCALE);
                } else if (et == 0) {  // K: fp16, compacted
                    const int p0 = sPos[r0], p1 = sPos[r1];
                    if (p0 >= 0)
                        g_Khf[(((size_t)(b * HH + h)) * LL + p0) * 8 + wd] =
                            h16pack(c1, c0);
                    if (p1 >= 0)
                        g_Khf[(((size_t)(b * HH + h)) * LL + p1) * 8 + wd] =
                            h16pack(c3, c2);
                } else {  // V: fp16 transposed, compacted
                    const int p0 = sPos[r0], p1 = sPos[r1];
                    const int dh = e & 15;
                    const size_t base = ((size_t)(b * HH + h)) * DHH;
                    if (p0 >= 0) {
                        g_Vth[(base + dh) * LL + p0] = __float2half_rn(c0);
                        g_Vth[(base + dh + 1) * LL + p0] = __float2half_rn(c1);
                    }
                    if (p1 >= 0) {
                        g_Vth[(base + dh) * LL + p1] = __float2half_rn(c2);
                        g_Vth[(base + dh + 1) * LL + p1] = __float2half_rn(c3);
                    }
                }
            }
        }
    }
}

// ============================================================
// fp16 HMMA flash attention (byte-identical to R16): 512 q/CTA,
// 256 threads (2 warp-groups sharing the K/V smem pipeline),
// key tiles of 128, cp.async double-buffered (nv8 predicates),
// shift-free softmax. Grid (4, 64) = 256 CTAs, 2 CTAs/SM.
// ============================================================
#define KT 128
#define KSTR 12   // K row: 8 data words + 4 pad (conflict-free B-frags)
#define VSTR 68   // V row: 64 data words + 4 pad (conflict-free B-frags)

__global__ __launch_bounds__(256, 2) void attn_kernel(float* __restrict__ out) {
    __shared__ uint32_t sKf[2][KT * KSTR];
    __shared__ uint32_t sVf[2][16 * VSTR];

    const int tid = threadIdx.x;
    const int wg = tid >> 7;              // warp-group 0/1
    const int wtid = tid & 127;
    const int lane = tid & 31, w = (wtid >> 5);
    const int r = lane >> 2, cq = lane & 3;
    const int bh = blockIdx.y, b = bh >> 3, hd = bh & 7;
    const int q0 = blockIdx.x * 512 + wg * 256;

    const int nv = g_cnt[b];
    const int nv8 = (nv + 7) & ~7;
    const int nt = (nv + KT - 1) / KT;

    // Q A-fragments (single fp16) for both halves of this group's window
    uint32_t qh[2][2][4];
#pragma unroll
    for (int hf = 0; hf < 2; hf++)
#pragma unroll
        for (int mt = 0; mt < 2; mt++) {
            const int row = q0 + hf * 128 + w * 32 + mt * 16 + r;
#pragma unroll
            for (int k = 0; k < 4; k++) {
                const int rr = row + (k & 1) * 8;
                const int wd = cq + (k >> 1) * 4;
                qh[hf][mt][k] = g_Qhf[((size_t)bh * LL + rr) * 8 + wd];
            }
        }

    // cp.async per-thread constants (256 threads: 1 K + 1 V copy each)
    const uint32_t aK = (uint32_t)__cvta_generic_to_shared(sKf);
    const uint32_t aV = (uint32_t)__cvta_generic_to_shared(sVf);
    const int krow = tid >> 1, kpart = tid & 1;
    const int vdh = tid >> 4, vrest = tid & 15;
    const int vch = vrest >> 1, vpart = vrest & 1;
    const uint32_t koff = (uint32_t)(krow * KSTR) * 4 + kpart * 16;
    const uint32_t voff = (uint32_t)(vdh * VSTR + vch * 8) * 4 + vpart * 16;
    const uint32_t kbufsz = KT * KSTR * 4, vbufsz = 16 * VSTR * 4;

    auto issue = [&](int bi, int k0) {
        const int ksz = (k0 + krow < nv8) ? 16 : 0;
        cpasync16(aK + bi * kbufsz + koff,
                  &g_Khf[((size_t)bh * LL + k0 + krow) * 8 + kpart * 4], ksz);
        const int vsz = (k0 + vch * 16 + vpart * 8 < nv8) ? 16 : 0;
        cpasync16(aV + bi * vbufsz + voff,
                  &g_Vth[((size_t)bh * DHH + vdh) * LL + k0 + vch * 16 + vpart * 8],
                  vsz);
    };

    float O[2][2][2][4];  // [half][mt][n]
#pragma unroll
    for (int hf = 0; hf < 2; hf++)
#pragma unroll
        for (int mt = 0; mt < 2; mt++)
#pragma unroll
            for (int n = 0; n < 2; n++)
#pragma unroll
                for (int k = 0; k < 4; k++) O[hf][mt][n][k] = 0.f;
    float rs[2][2][2] = {};  // [half][mt][row half]

    issue(0, 0);
    CP_COMMIT();

    for (int t = 0; t < nt; t++) {
        CP_WAIT0();
        __syncthreads();
        if (t + 1 < nt) issue((t + 1) & 1, (t + 1) * KT);
        CP_COMMIT();

        const uint32_t* Kf = sKf[t & 1];
        const uint32_t* Vf = sVf[t & 1];

#pragma unroll
        for (int s = 0; s < 8; s++) {   // 16-key chunks
#pragma unroll
            for (int hf = 0; hf < 2; hf++) {
                float S[2][2][4];
#pragma unroll
                for (int mt = 0; mt < 2; mt++)
#pragma unroll
                    for (int n = 0; n < 2; n++)
#pragma unroll
                        for (int k = 0; k < 4; k++) S[mt][n][k] = 0.f;

#pragma unroll
                for (int n = 0; n < 2; n++) {
                    const int kw = (s * 16 + n * 8 + r) * KSTR + cq;
                    const uint32_t k0w = Kf[kw], k1w = Kf[kw + 4];
#pragma unroll
                    for (int mt = 0; mt < 2; mt++)
                        mma16816h(S[mt][n], qh[hf][mt], k0w, k1w);
                }

                uint32_t ph[2][4];
#pragma unroll
                for (int mt = 0; mt < 2; mt++) {
                    float p[2][4];
#pragma unroll
                    for (int n = 0; n < 2; n++) {
#pragma unroll
                        for (int k = 0; k < 4; k++)
                            p[n][k] = ex2f(S[mt][n][k]);   // shift-free
                        rs[hf][mt][0] += p[n][0] + p[n][1];
                        rs[hf][mt][1] += p[n][2] + p[n][3];
                    }
                    ph[mt][0] = h16pack(p[0][1], p[0][0]);
                    ph[mt][1] = h16pack(p[0][3], p[0][2]);
                    ph[mt][2] = h16pack(p[1][1], p[1][0]);
                    ph[mt][3] = h16pack(p[1][3], p[1][2]);
                }

#pragma unroll
                for (int n = 0; n < 2; n++) {
                    const int vw = (n * 8 + r) * VSTR + s * 8 + cq;
                    const uint32_t v0 = Vf[vw], v1 = Vf[vw + 4];
#pragma unroll
                    for (int mt = 0; mt < 2; mt++)
                        mma16816h(O[hf][mt][n], ph[mt], v0, v1);
                }
            }
        }
    }

    // pads: zero K rows -> S=0 -> p=1 each; subtract exactly
    const float pad = (float)(nt * KT - nv);
#pragma unroll
    for (int hf = 0; hf < 2; hf++) {
        float inv[2][2];
#pragma unroll
        for (int mt = 0; mt < 2; mt++)
#pragma unroll
            for (int rh = 0; rh < 2; rh++) {
                float v = rs[hf][mt][rh];
                v += __shfl_xor_sync(0xffffffffu, v, 1);
                v += __shfl_xor_sync(0xffffffffu, v, 2);
                inv[mt][rh] = 1.f / (v - pad);
            }
#pragma unroll
        for (int mt = 0; mt < 2; mt++) {
            const int q = q0 + hf * 128 + w * 32 + mt * 16 + r;
#pragma unroll
            for (int n = 0; n < 2; n++) {
                const int dh = hd * DHH + n * 8 + cq * 2;
                out[((size_t)b * DD + dh) * LL + q] = O[hf][mt][n][0] * inv[mt][0];
                out[((size_t)b * DD + dh + 1) * LL + q] = O[hf][mt][n][1] * inv[mt][0];
                out[((size_t)b * DD + dh) * LL + q + 8] = O[hf][mt][n][2] * inv[mt][1];
                out[((size_t)b * DD + dh + 1) * LL + q + 8] =
                    O[hf][mt][n][3] * inv[mt][1];
            }
        }
    }
}

extern "C" void kernel_launch(void* const* d_in, const int* in_sizes, int n_in,
                              void* d_out, int out_size) {
    const float* queries = (const float*)d_in[0];
    const int* mask = (const int*)d_in[1];
    const float* W_mem = (const float*)d_in[2];
    const float* W_q = (const float*)d_in[3];
    float* out = (float*)d_out;

    cudaFuncSetAttribute(proj_kernel, cudaFuncAttributeMaxDynamicSharedMemorySize,
                         PROJ_SMEM);
    proj_kernel<<<16 * BB, 256, PROJ_SMEM>>>(queries, mask, W_mem, W_q);
    attn_kernel<<<dim3(LL / 512, BB * HH), 256>>>(out);
}